// round 4
// baseline (speedup 1.0000x reference)
#include <cuda_runtime.h>

#define NN 100000
#define EE 1600000
#define HD 64
#define CC 40
#define BN_EPS 1e-5f

// ---------------- device scratch (static globals; no runtime allocation) ----------------
__device__ int   g_mode;          // 0 = edge_index int32, 1 = int64
__device__ int   g_esrc[EE];
__device__ int   g_edst[EE];
__device__ int   g_deg[NN];
__device__ int   g_off[NN];
__device__ int   g_cur[NN];
__device__ int   g_srcs[EE];
__device__ __align__(16) float g_agg [NN * HD];
__device__ __align__(16) float g_pre [NN * HD];
__device__ __align__(16) float g_act1[NN * HD];
__device__ float g_sums[2 * HD];
__device__ float g_bnA[HD];
__device__ float g_bnB[HD];

// ---------------- edge dtype detection ----------------
// For int64 data (ids < 2^31), every odd 32-bit word of the first 64 is a zero
// high-word. For int32 data those words are uniform node ids. All sampled
// words lie within the buffer under either dtype.
__global__ void k_detect(const int* __restrict__ p32) {
    if (threadIdx.x == 0 && blockIdx.x == 0) {
        int allz = 1;
        for (int i = 0; i < 32; i++)
            if (p32[2 * i + 1] != 0) allz = 0;
        g_mode = allz;
    }
}

// ---------------- CSR build ----------------
__global__ void k_zero_counters() {
    int i = blockIdx.x * blockDim.x + threadIdx.x;
    if (i < NN) { g_deg[i] = 0; g_cur[i] = 0; }
}

// normalize edges to int32 and histogram destination degrees
__global__ void k_norm_hist(const int* __restrict__ p32) {
    int e = blockIdx.x * blockDim.x + threadIdx.x;
    if (e < EE) {
        int s, d;
        if (g_mode) {                     // int64 source data: read low words
            s = p32[2 * e];
            d = p32[2 * EE + 2 * e];
        } else {                          // int32 source data
            s = p32[e];
            d = p32[EE + e];
        }
        g_esrc[e] = s;
        g_edst[e] = d;
        atomicAdd(&g_deg[d], 1);
    }
}

// single-block exclusive scan over g_deg -> g_off
__global__ void k_scan() {
    __shared__ int ss[1024];
    int tid = threadIdx.x;
    const int chunk = (NN + 1023) / 1024;
    int b = tid * chunk;
    int e = min(b + chunk, NN);
    int s = 0;
    for (int i = b; i < e; i++) s += g_deg[i];
    ss[tid] = s;
    __syncthreads();
    for (int d = 1; d < 1024; d <<= 1) {
        int v = (tid >= d) ? ss[tid - d] : 0;
        __syncthreads();
        ss[tid] += v;
        __syncthreads();
    }
    int run = (tid == 0) ? 0 : ss[tid - 1];
    for (int i = b; i < e; i++) { g_off[i] = run; run += g_deg[i]; }
}

__global__ void k_build() {
    int e = blockIdx.x * blockDim.x + threadIdx.x;
    if (e < EE) {
        int s = g_esrc[e];
        int d = g_edst[e];
        int p = atomicAdd(&g_cur[d], 1);
        g_srcs[g_off[d] + p] = s;
    }
}

// ---------------- mean aggregation: 16 threads per node, float4 gather ----------------
// use_global_in: 0 -> read from xin (harness input), 1 -> read from g_act1
__global__ void k_agg(const float* __restrict__ xin, int use_global_in) {
    const float4* __restrict__ in =
        use_global_in ? (const float4*)g_act1 : (const float4*)xin;
    int node = blockIdx.x * 8 + (threadIdx.x >> 4);
    int c4   = threadIdx.x & 15;
    if (node >= NN) return;
    int off = g_off[node];
    int d   = g_deg[node];
    float4 acc = make_float4(0.f, 0.f, 0.f, 0.f);
    int j = 0;
    for (; j + 2 <= d; j += 2) {
        int s0 = g_srcs[off + j];
        int s1 = g_srcs[off + j + 1];
        float4 v0 = __ldg(&in[(size_t)s0 * 16 + c4]);
        float4 v1 = __ldg(&in[(size_t)s1 * 16 + c4]);
        acc.x += v0.x + v1.x;
        acc.y += v0.y + v1.y;
        acc.z += v0.z + v1.z;
        acc.w += v0.w + v1.w;
    }
    if (j < d) {
        int s0 = g_srcs[off + j];
        float4 v0 = __ldg(&in[(size_t)s0 * 16 + c4]);
        acc.x += v0.x; acc.y += v0.y; acc.z += v0.z; acc.w += v0.w;
    }
    float inv = 1.f / (float)max(d, 1);
    acc.x *= inv; acc.y *= inv; acc.z *= inv; acc.w *= inv;
    ((float4*)g_agg)[(size_t)node * 16 + c4] = acc;
}

// ---------------- fused dual GEMM: g_pre = g_agg@Wl^T + bl + X@Wr^T ----------------
// 256 threads, 64 nodes/block, thread tile 4 nodes x 4 channels.
// Two K=64 phases sharing 2x16KB static smem tiles (k-major, XOR-swizzled).
__global__ void k_gemm(const float* __restrict__ Xext, int use_global_x,
                       const float* __restrict__ Wl, const float* __restrict__ bl,
                       const float* __restrict__ Wr) {
    __shared__ float xs[64 * 64];   // [k][n] swizzled
    __shared__ float ws[64 * 64];   // [k][c] swizzled
    int tid = threadIdx.x;
    int node0 = blockIdx.x * 64;
    const float* __restrict__ Xp = use_global_x ? (const float*)g_act1 : Xext;

    int c0 = (tid & 15) * 4;
    int n0 = (tid >> 4) * 4;

    float acc[4][4];
#pragma unroll
    for (int j = 0; j < 4; j++) {
        float b = __ldg(&bl[c0 + j]);
#pragma unroll
        for (int i = 0; i < 4; i++) acc[i][j] = b;
    }

#pragma unroll
    for (int ph = 0; ph < 2; ph++) {
        const float* __restrict__ src = ph ? Xp : (const float*)g_agg;
        const float* __restrict__ W   = ph ? Wr : Wl;

        for (int idx = tid; idx < 4096; idx += 256) {
            int n = idx >> 6, k = idx & 63;
            int gn = node0 + n;
            float v = (gn < NN) ? src[(size_t)gn * HD + k] : 0.f;
            xs[k * 64 + (n ^ ((k & 15) << 2))] = v;
        }
        for (int idx = tid; idx < 4096; idx += 256) {
            int c = idx >> 6, k = idx & 63;
            ws[k * 64 + (c ^ ((k & 15) << 2))] = W[idx];
        }
        __syncthreads();

#pragma unroll 8
        for (int k = 0; k < 64; k++) {
            int sw = (k & 15) << 2;
            float4 wv = *reinterpret_cast<const float4*>(&ws[k * 64 + (c0 ^ sw)]);
            float4 xv = *reinterpret_cast<const float4*>(&xs[k * 64 + (n0 ^ sw)]);
            float wr[4] = {wv.x, wv.y, wv.z, wv.w};
            float xr[4] = {xv.x, xv.y, xv.z, xv.w};
#pragma unroll
            for (int i = 0; i < 4; i++)
#pragma unroll
                for (int j = 0; j < 4; j++)
                    acc[i][j] += xr[i] * wr[j];
        }
        __syncthreads();
    }

#pragma unroll
    for (int i = 0; i < 4; i++) {
        int gn = node0 + n0 + i;
        if (gn < NN) {
            float4 v = make_float4(acc[i][0], acc[i][1], acc[i][2], acc[i][3]);
            *reinterpret_cast<float4*>(&g_pre[(size_t)gn * HD + c0]) = v;
        }
    }
}

// ---------------- BatchNorm ----------------
__global__ void k_zero_sums() {
    int i = threadIdx.x;
    if (i < 2 * HD) g_sums[i] = 0.f;
}

__global__ void k_bnstats() {
    int ch   = threadIdx.x & 63;
    int row0 = blockIdx.x * 4 + (threadIdx.x >> 6);
    float s = 0.f, s2 = 0.f;
    for (int n = row0; n < NN; n += gridDim.x * 4) {
        float v = g_pre[(size_t)n * HD + ch];
        s += v; s2 += v * v;
    }
    __shared__ float sh[256], sh2[256];
    sh[threadIdx.x] = s; sh2[threadIdx.x] = s2;
    __syncthreads();
    if (threadIdx.x < 64) {
        float ts = sh[threadIdx.x] + sh[64 + threadIdx.x] + sh[128 + threadIdx.x] + sh[192 + threadIdx.x];
        float t2 = sh2[threadIdx.x] + sh2[64 + threadIdx.x] + sh2[128 + threadIdx.x] + sh2[192 + threadIdx.x];
        atomicAdd(&g_sums[ch], ts);
        atomicAdd(&g_sums[HD + ch], t2);
    }
}

__global__ void k_bnfin(const float* __restrict__ g, const float* __restrict__ beta) {
    int ch = threadIdx.x;
    if (ch < HD) {
        float mu  = g_sums[ch] / (float)NN;
        float var = g_sums[HD + ch] / (float)NN - mu * mu;
        float a   = g[ch] * rsqrtf(var + BN_EPS);
        g_bnA[ch] = a;
        g_bnB[ch] = beta[ch] - mu * a;
    }
}

// use_ext_out: 0 -> write g_act1, 1 -> write outext (harness d_out region)
__global__ void k_bnapply(float* __restrict__ outext, int use_ext_out) {
    float* __restrict__ out = use_ext_out ? outext : (float*)g_act1;
    int i = blockIdx.x * blockDim.x + threadIdx.x;
    if (i < NN * HD) {
        int ch  = i & 63;
        float y = g_pre[i] * g_bnA[ch] + g_bnB[ch];
        out[i]  = y > 0.f ? y : 0.f;
    }
}

// ---------------- decoder: logits = h @ Wd^T + bd ----------------
__global__ void k_dec(const float* __restrict__ h, const float* __restrict__ Wd,
                      const float* __restrict__ bd, float* __restrict__ out) {
    __shared__ float wd[CC * 65];    // 10.4 KB
    __shared__ float hs[128 * 65];   // 33.3 KB
    int tid = threadIdx.x;
    for (int idx = tid; idx < CC * HD; idx += 256) {
        int c = idx / HD, k = idx % HD;
        wd[c * 65 + k] = Wd[idx];
    }
    int node0 = blockIdx.x * 128;
    for (int idx = tid; idx < 128 * HD; idx += 256) {
        int n = idx >> 6, k = idx & 63;
        int gn = node0 + n;
        hs[n * 65 + k] = (gn < NN) ? h[(size_t)gn * HD + k] : 0.f;
    }
    __syncthreads();

    int c0 = (tid & 3) * 10;
    int n0 = (tid >> 2) * 2;

    float acc[2][10];
#pragma unroll
    for (int j = 0; j < 10; j++) {
        float b = __ldg(&bd[c0 + j]);
        acc[0][j] = b; acc[1][j] = b;
    }
#pragma unroll 4
    for (int k = 0; k < 64; k++) {
        float w[10];
#pragma unroll
        for (int j = 0; j < 10; j++) w[j] = wd[(c0 + j) * 65 + k];
        float a0 = hs[n0 * 65 + k];
        float a1 = hs[(n0 + 1) * 65 + k];
#pragma unroll
        for (int j = 0; j < 10; j++) {
            acc[0][j] += a0 * w[j];
            acc[1][j] += a1 * w[j];
        }
    }
#pragma unroll
    for (int i = 0; i < 2; i++) {
        int gn = node0 + n0 + i;
        if (gn < NN) {
#pragma unroll
            for (int j = 0; j < 10; j++)
                out[(size_t)gn * CC + c0 + j] = acc[i][j];
        }
    }
}

// ---------------- launcher: ONLY kernel launches, no other CUDA API ----------------
extern "C" void kernel_launch(void* const* d_in, const int* in_sizes, int n_in,
                              void* d_out, int out_size) {
    const float* x   = (const float*)d_in[0];
    const int*   ei  = (const int*)d_in[1];     // dtype resolved on device
    const float* W1l = (const float*)d_in[2];
    const float* b1l = (const float*)d_in[3];
    const float* W1r = (const float*)d_in[4];
    const float* g1  = (const float*)d_in[5];
    const float* be1 = (const float*)d_in[6];
    const float* W2l = (const float*)d_in[7];
    const float* b2l = (const float*)d_in[8];
    const float* W2r = (const float*)d_in[9];
    const float* g2  = (const float*)d_in[10];
    const float* be2 = (const float*)d_in[11];
    const float* Wd  = (const float*)d_in[12];
    const float* bd  = (const float*)d_in[13];

    float* outp   = (float*)d_out;
    float* logits = outp;                       // [N, C]
    float* hout   = outp + (size_t)NN * CC;     // [N, H]

    // CSR build
    k_detect<<<1, 32>>>(ei);
    k_zero_counters<<<(NN + 255) / 256, 256>>>();
    k_norm_hist<<<(EE + 255) / 256, 256>>>(ei);
    k_scan<<<1, 1024>>>();
    k_build<<<(EE + 255) / 256, 256>>>();

    // Layer 1
    k_agg<<<(NN + 7) / 8, 128>>>(x, 0);
    k_gemm<<<(NN + 63) / 64, 256>>>(x, 0, W1l, b1l, W1r);
    k_zero_sums<<<1, 128>>>();
    k_bnstats<<<256, 256>>>();
    k_bnfin<<<1, 64>>>(g1, be1);
    k_bnapply<<<(NN * HD + 255) / 256, 256>>>(nullptr, 0);

    // Layer 2
    k_agg<<<(NN + 7) / 8, 128>>>(nullptr, 1);
    k_gemm<<<(NN + 63) / 64, 256>>>(nullptr, 1, W2l, b2l, W2r);
    k_zero_sums<<<1, 128>>>();
    k_bnstats<<<256, 256>>>();
    k_bnfin<<<1, 64>>>(g2, be2);
    k_bnapply<<<(NN * HD + 255) / 256, 256>>>(hout, 1);

    // Decoder
    k_dec<<<(NN + 127) / 128, 256>>>(hout, Wd, bd, logits);
}

// round 5
// speedup vs baseline: 1.2538x; 1.2538x over previous
#include <cuda_runtime.h>

#define NN 100000
#define EE 1600000
#define HD 64
#define CC 40
#define BN_EPS 1e-5f
#define SCAN_NBLK ((NN + 1023) / 1024)   // 98

// ---------------- device scratch (static globals; no runtime allocation) ----------------
__device__ int   g_mode;          // 0 = edge_index int32, 1 = int64
__device__ int   g_edst[EE];
__device__ int   g_deg[NN];
__device__ int   g_off[NN];
__device__ int   g_cur[NN];
__device__ int   g_srcs[EE];
__device__ int   g_bsum[SCAN_NBLK];
__device__ int   g_bpre[SCAN_NBLK];
__device__ __align__(16) float g_agg [NN * HD];
__device__ __align__(16) float g_pre [NN * HD];
__device__ __align__(16) float g_act1[NN * HD];
__device__ float g_sums[2 * HD];
__device__ float g_bnA[HD];
__device__ float g_bnB[HD];

// ---------------- edge dtype detection ----------------
// For int64 data (ids < 2^31) every odd 32-bit word of the first 64 is a zero
// high-word; for int32 data those words are uniform node ids.
__global__ void k_detect(const int* __restrict__ p32) {
    if (threadIdx.x == 0 && blockIdx.x == 0) {
        int allz = 1;
        for (int i = 0; i < 32; i++)
            if (p32[2 * i + 1] != 0) allz = 0;
        g_mode = allz;
    }
}

// ---------------- CSR build ----------------
__global__ void k_zero_counters() {
    int i = blockIdx.x * blockDim.x + threadIdx.x;
    if (i < NN) { g_deg[i] = 0; g_cur[i] = 0; }
}

// read dst ids (dtype-resolved), cache them, histogram degrees
__global__ void k_hist(const int* __restrict__ p32) {
    int e = blockIdx.x * blockDim.x + threadIdx.x;
    if (e < EE) {
        int d = g_mode ? p32[2 * EE + 2 * e] : p32[EE + e];
        g_edst[e] = d;
        atomicAdd(&g_deg[d], 1);
    }
}

// ---- grid-wide exclusive scan of g_deg -> g_off (3 phases) ----
__global__ void k_scan1() {
    __shared__ int ss[1024];
    int tid = threadIdx.x;
    int i = blockIdx.x * 1024 + tid;
    int v = (i < NN) ? g_deg[i] : 0;
    ss[tid] = v;
    __syncthreads();
#pragma unroll
    for (int d = 1; d < 1024; d <<= 1) {
        int t = (tid >= d) ? ss[tid - d] : 0;
        __syncthreads();
        ss[tid] += t;
        __syncthreads();
    }
    if (i < NN) g_off[i] = ss[tid] - v;               // block-local exclusive
    if (tid == 1023) g_bsum[blockIdx.x] = ss[1023];    // block total
}

__global__ void k_scan2() {
    __shared__ int ss[128];
    int tid = threadIdx.x;
    int v = (tid < SCAN_NBLK) ? g_bsum[tid] : 0;
    ss[tid] = v;
    __syncthreads();
#pragma unroll
    for (int d = 1; d < 128; d <<= 1) {
        int t = (tid >= d) ? ss[tid - d] : 0;
        __syncthreads();
        ss[tid] += t;
        __syncthreads();
    }
    if (tid < SCAN_NBLK) g_bpre[tid] = ss[tid] - v;    // exclusive block prefix
}

__global__ void k_scan3() {
    int i = blockIdx.x * blockDim.x + threadIdx.x;
    if (i < NN) g_off[i] += g_bpre[i >> 10];
}

// scatter src ids into CSR order (src read directly from input by mode)
__global__ void k_build(const int* __restrict__ p32) {
    int e = blockIdx.x * blockDim.x + threadIdx.x;
    if (e < EE) {
        int s = g_mode ? p32[2 * e] : p32[e];
        int d = g_edst[e];
        int p = atomicAdd(&g_cur[d], 1);
        g_srcs[g_off[d] + p] = s;
    }
}

// ---------------- mean aggregation: 16 threads per node, float4 gather ----------------
__global__ void k_agg(const float* __restrict__ xin, int use_global_in) {
    const float4* __restrict__ in =
        use_global_in ? (const float4*)g_act1 : (const float4*)xin;
    int node = blockIdx.x * 8 + (threadIdx.x >> 4);
    int c4   = threadIdx.x & 15;
    if (node >= NN) return;
    int off = g_off[node];
    int d   = g_deg[node];
    float4 acc = make_float4(0.f, 0.f, 0.f, 0.f);
    int j = 0;
    for (; j + 2 <= d; j += 2) {
        int s0 = g_srcs[off + j];
        int s1 = g_srcs[off + j + 1];
        float4 v0 = __ldg(&in[(size_t)s0 * 16 + c4]);
        float4 v1 = __ldg(&in[(size_t)s1 * 16 + c4]);
        acc.x += v0.x + v1.x;
        acc.y += v0.y + v1.y;
        acc.z += v0.z + v1.z;
        acc.w += v0.w + v1.w;
    }
    if (j < d) {
        int s0 = g_srcs[off + j];
        float4 v0 = __ldg(&in[(size_t)s0 * 16 + c4]);
        acc.x += v0.x; acc.y += v0.y; acc.z += v0.z; acc.w += v0.w;
    }
    float inv = 1.f / (float)max(d, 1);
    acc.x *= inv; acc.y *= inv; acc.z *= inv; acc.w *= inv;
    ((float4*)g_agg)[(size_t)node * 16 + c4] = acc;
}

// ---------------- fused dual GEMM: g_pre = g_agg@Wl^T + bl + X@Wr^T ----------------
__global__ void k_gemm(const float* __restrict__ Xext, int use_global_x,
                       const float* __restrict__ Wl, const float* __restrict__ bl,
                       const float* __restrict__ Wr) {
    __shared__ float xs[64 * 64];   // [k][n] swizzled
    __shared__ float ws[64 * 64];   // [k][c] swizzled
    int tid = threadIdx.x;
    int node0 = blockIdx.x * 64;
    const float* __restrict__ Xp = use_global_x ? (const float*)g_act1 : Xext;

    int c0 = (tid & 15) * 4;
    int n0 = (tid >> 4) * 4;

    float acc[4][4];
#pragma unroll
    for (int j = 0; j < 4; j++) {
        float b = __ldg(&bl[c0 + j]);
#pragma unroll
        for (int i = 0; i < 4; i++) acc[i][j] = b;
    }

#pragma unroll
    for (int ph = 0; ph < 2; ph++) {
        const float* __restrict__ src = ph ? Xp : (const float*)g_agg;
        const float* __restrict__ W   = ph ? Wr : Wl;

        for (int idx = tid; idx < 4096; idx += 256) {
            int n = idx >> 6, k = idx & 63;
            int gn = node0 + n;
            float v = (gn < NN) ? src[(size_t)gn * HD + k] : 0.f;
            xs[k * 64 + (n ^ ((k & 15) << 2))] = v;
        }
        for (int idx = tid; idx < 4096; idx += 256) {
            int c = idx >> 6, k = idx & 63;
            ws[k * 64 + (c ^ ((k & 15) << 2))] = W[idx];
        }
        __syncthreads();

#pragma unroll 8
        for (int k = 0; k < 64; k++) {
            int sw = (k & 15) << 2;
            float4 wv = *reinterpret_cast<const float4*>(&ws[k * 64 + (c0 ^ sw)]);
            float4 xv = *reinterpret_cast<const float4*>(&xs[k * 64 + (n0 ^ sw)]);
            float wr[4] = {wv.x, wv.y, wv.z, wv.w};
            float xr[4] = {xv.x, xv.y, xv.z, xv.w};
#pragma unroll
            for (int i = 0; i < 4; i++)
#pragma unroll
                for (int j = 0; j < 4; j++)
                    acc[i][j] += xr[i] * wr[j];
        }
        __syncthreads();
    }

#pragma unroll
    for (int i = 0; i < 4; i++) {
        int gn = node0 + n0 + i;
        if (gn < NN) {
            float4 v = make_float4(acc[i][0], acc[i][1], acc[i][2], acc[i][3]);
            *reinterpret_cast<float4*>(&g_pre[(size_t)gn * HD + c0]) = v;
        }
    }
}

// ---------------- BatchNorm ----------------
__global__ void k_zero_sums() {
    int i = threadIdx.x;
    if (i < 2 * HD) g_sums[i] = 0.f;
}

__global__ void k_bnstats() {
    int ch   = threadIdx.x & 63;
    int row0 = blockIdx.x * 4 + (threadIdx.x >> 6);
    float s = 0.f, s2 = 0.f;
    for (int n = row0; n < NN; n += gridDim.x * 4) {
        float v = g_pre[(size_t)n * HD + ch];
        s += v; s2 += v * v;
    }
    __shared__ float sh[256], sh2[256];
    sh[threadIdx.x] = s; sh2[threadIdx.x] = s2;
    __syncthreads();
    if (threadIdx.x < 64) {
        float ts = sh[threadIdx.x] + sh[64 + threadIdx.x] + sh[128 + threadIdx.x] + sh[192 + threadIdx.x];
        float t2 = sh2[threadIdx.x] + sh2[64 + threadIdx.x] + sh2[128 + threadIdx.x] + sh2[192 + threadIdx.x];
        atomicAdd(&g_sums[ch], ts);
        atomicAdd(&g_sums[HD + ch], t2);
    }
}

__global__ void k_bnfin(const float* __restrict__ g, const float* __restrict__ beta) {
    int ch = threadIdx.x;
    if (ch < HD) {
        float mu  = g_sums[ch] / (float)NN;
        float var = g_sums[HD + ch] / (float)NN - mu * mu;
        float a   = g[ch] * rsqrtf(var + BN_EPS);
        g_bnA[ch] = a;
        g_bnB[ch] = beta[ch] - mu * a;
    }
}

__global__ void k_bnapply(float* __restrict__ outext, int use_ext_out) {
    float* __restrict__ out = use_ext_out ? outext : (float*)g_act1;
    int i = blockIdx.x * blockDim.x + threadIdx.x;
    if (i < NN * HD) {
        int ch  = i & 63;
        float y = g_pre[i] * g_bnA[ch] + g_bnB[ch];
        out[i]  = y > 0.f ? y : 0.f;
    }
}

// ---------------- decoder: logits = h @ Wd^T + bd ----------------
__global__ void k_dec(const float* __restrict__ h, const float* __restrict__ Wd,
                      const float* __restrict__ bd, float* __restrict__ out) {
    __shared__ float wd[CC * 65];
    __shared__ float hs[128 * 65];
    int tid = threadIdx.x;
    for (int idx = tid; idx < CC * HD; idx += 256) {
        int c = idx / HD, k = idx % HD;
        wd[c * 65 + k] = Wd[idx];
    }
    int node0 = blockIdx.x * 128;
    for (int idx = tid; idx < 128 * HD; idx += 256) {
        int n = idx >> 6, k = idx & 63;
        int gn = node0 + n;
        hs[n * 65 + k] = (gn < NN) ? h[(size_t)gn * HD + k] : 0.f;
    }
    __syncthreads();

    int c0 = (tid & 3) * 10;
    int n0 = (tid >> 2) * 2;

    float acc[2][10];
#pragma unroll
    for (int j = 0; j < 10; j++) {
        float b = __ldg(&bd[c0 + j]);
        acc[0][j] = b; acc[1][j] = b;
    }
#pragma unroll 4
    for (int k = 0; k < 64; k++) {
        float w[10];
#pragma unroll
        for (int j = 0; j < 10; j++) w[j] = wd[(c0 + j) * 65 + k];
        float a0 = hs[n0 * 65 + k];
        float a1 = hs[(n0 + 1) * 65 + k];
#pragma unroll
        for (int j = 0; j < 10; j++) {
            acc[0][j] += a0 * w[j];
            acc[1][j] += a1 * w[j];
        }
    }
#pragma unroll
    for (int i = 0; i < 2; i++) {
        int gn = node0 + n0 + i;
        if (gn < NN) {
#pragma unroll
            for (int j = 0; j < 10; j++)
                out[(size_t)gn * CC + c0 + j] = acc[i][j];
        }
    }
}

// ---------------- launcher: ONLY kernel launches, no other CUDA API ----------------
extern "C" void kernel_launch(void* const* d_in, const int* in_sizes, int n_in,
                              void* d_out, int out_size) {
    const float* x   = (const float*)d_in[0];
    const int*   ei  = (const int*)d_in[1];     // dtype resolved on device
    const float* W1l = (const float*)d_in[2];
    const float* b1l = (const float*)d_in[3];
    const float* W1r = (const float*)d_in[4];
    const float* g1  = (const float*)d_in[5];
    const float* be1 = (const float*)d_in[6];
    const float* W2l = (const float*)d_in[7];
    const float* b2l = (const float*)d_in[8];
    const float* W2r = (const float*)d_in[9];
    const float* g2  = (const float*)d_in[10];
    const float* be2 = (const float*)d_in[11];
    const float* Wd  = (const float*)d_in[12];
    const float* bd  = (const float*)d_in[13];

    float* outp   = (float*)d_out;
    float* logits = outp;                       // [N, C]
    float* hout   = outp + (size_t)NN * CC;     // [N, H]

    // CSR build
    k_detect<<<1, 32>>>(ei);
    k_zero_counters<<<(NN + 255) / 256, 256>>>();
    k_hist<<<(EE + 255) / 256, 256>>>(ei);
    k_scan1<<<SCAN_NBLK, 1024>>>();
    k_scan2<<<1, 128>>>();
    k_scan3<<<(NN + 255) / 256, 256>>>();
    k_build<<<(EE + 255) / 256, 256>>>(ei);

    // Layer 1
    k_agg<<<(NN + 7) / 8, 128>>>(x, 0);
    k_gemm<<<(NN + 63) / 64, 256>>>(x, 0, W1l, b1l, W1r);
    k_zero_sums<<<1, 128>>>();
    k_bnstats<<<256, 256>>>();
    k_bnfin<<<1, 64>>>(g1, be1);
    k_bnapply<<<(NN * HD + 255) / 256, 256>>>(nullptr, 0);

    // Layer 2
    k_agg<<<(NN + 7) / 8, 128>>>(nullptr, 1);
    k_gemm<<<(NN + 63) / 64, 256>>>(nullptr, 1, W2l, b2l, W2r);
    k_zero_sums<<<1, 128>>>();
    k_bnstats<<<256, 256>>>();
    k_bnfin<<<1, 64>>>(g2, be2);
    k_bnapply<<<(NN * HD + 255) / 256, 256>>>(hout, 1);

    // Decoder
    k_dec<<<(NN + 127) / 128, 256>>>(hout, Wd, bd, logits);
}

// round 8
// speedup vs baseline: 1.4704x; 1.1727x over previous
#include <cuda_runtime.h>

#define NN 100000
#define EE 1600000
#define HD 64
#define CC 40
#define BN_EPS 1e-5f
#define SCAN_NBLK ((NN + 1023) / 1024)   // 98

// ---------------- device scratch (static globals; no runtime allocation) ----------------
__device__ int   g_mode;          // 0 = edge_index int32, 1 = int64
__device__ int   g_edst[EE];
__device__ int   g_deg[NN];
__device__ int   g_off[NN];
__device__ int   g_cur[NN];
__device__ int   g_srcs[EE];
__device__ int   g_bsum[SCAN_NBLK];
__device__ int   g_bpre[SCAN_NBLK];
__device__ __align__(16) float g_agg [NN * HD];
__device__ __align__(16) float g_pre [NN * HD];   // layer-1 pre-activation
__device__ __align__(16) float g_act1[NN * HD];   // layer-2 pre-activation
__device__ float g_sums[2 * HD];
__device__ __align__(16) float g_bnA[HD];
__device__ __align__(16) float g_bnB[HD];

// ---------------- edge dtype detection ----------------
__global__ void k_detect(const int* __restrict__ p32) {
    if (threadIdx.x == 0 && blockIdx.x == 0) {
        int allz = 1;
        for (int i = 0; i < 32; i++)
            if (p32[2 * i + 1] != 0) allz = 0;
        g_mode = allz;
    }
}

// ---------------- CSR build ----------------
__global__ void k_zero_counters() {
    int i = blockIdx.x * blockDim.x + threadIdx.x;
    if (i < NN) { g_deg[i] = 0; g_cur[i] = 0; }
}

__global__ void k_hist(const int* __restrict__ p32) {
    int e = blockIdx.x * blockDim.x + threadIdx.x;
    if (e < EE) {
        int d = g_mode ? p32[2 * EE + 2 * e] : p32[EE + e];
        g_edst[e] = d;
        atomicAdd(&g_deg[d], 1);
    }
}

__global__ void k_scan1() {
    __shared__ int ss[1024];
    int tid = threadIdx.x;
    int i = blockIdx.x * 1024 + tid;
    int v = (i < NN) ? g_deg[i] : 0;
    ss[tid] = v;
    __syncthreads();
#pragma unroll
    for (int d = 1; d < 1024; d <<= 1) {
        int t = (tid >= d) ? ss[tid - d] : 0;
        __syncthreads();
        ss[tid] += t;
        __syncthreads();
    }
    if (i < NN) g_off[i] = ss[tid] - v;
    if (tid == 1023) g_bsum[blockIdx.x] = ss[1023];
}

__global__ void k_scan2() {
    __shared__ int ss[128];
    int tid = threadIdx.x;
    int v = (tid < SCAN_NBLK) ? g_bsum[tid] : 0;
    ss[tid] = v;
    __syncthreads();
#pragma unroll
    for (int d = 1; d < 128; d <<= 1) {
        int t = (tid >= d) ? ss[tid - d] : 0;
        __syncthreads();
        ss[tid] += t;
        __syncthreads();
    }
    if (tid < SCAN_NBLK) g_bpre[tid] = ss[tid] - v;
}

__global__ void k_scan3() {
    int i = blockIdx.x * blockDim.x + threadIdx.x;
    if (i < NN) g_off[i] += g_bpre[i >> 10];
}

__global__ void k_build(const int* __restrict__ p32) {
    int e = blockIdx.x * blockDim.x + threadIdx.x;
    if (e < EE) {
        int s = g_mode ? p32[2 * e] : p32[e];
        int d = g_edst[e];
        int p = atomicAdd(&g_cur[d], 1);
        g_srcs[g_off[d] + p] = s;
    }
}

// ---------------- mean aggregation: 16 threads/node, float4 gather ----------------
// MODE 0: in = xin raw.  MODE 1: in = g_pre with BN1+ReLU applied on the fly.
__device__ __forceinline__ void xf_acc(float4& acc, float4 v,
                                       const float4& a4, const float4& b4, int mode) {
    if (mode) {
        v.x = fmaxf(fmaf(v.x, a4.x, b4.x), 0.f);
        v.y = fmaxf(fmaf(v.y, a4.y, b4.y), 0.f);
        v.z = fmaxf(fmaf(v.z, a4.z, b4.z), 0.f);
        v.w = fmaxf(fmaf(v.w, a4.w, b4.w), 0.f);
    }
    acc.x += v.x; acc.y += v.y; acc.z += v.z; acc.w += v.w;
}

template <int MODE>
__global__ void k_agg(const float* __restrict__ xin) {
    const float4* __restrict__ in = MODE ? (const float4*)g_pre : (const float4*)xin;
    int node = blockIdx.x * 8 + (threadIdx.x >> 4);
    int c4   = threadIdx.x & 15;
    if (node >= NN) return;

    float4 a4 = make_float4(1.f, 1.f, 1.f, 1.f);
    float4 b4 = make_float4(0.f, 0.f, 0.f, 0.f);
    if (MODE) {
        a4 = ((const float4*)g_bnA)[c4];
        b4 = ((const float4*)g_bnB)[c4];
    }

    int off = g_off[node];
    int d   = g_deg[node];
    float4 acc = make_float4(0.f, 0.f, 0.f, 0.f);

    int j = 0;
    for (; j + 4 <= d; j += 4) {
        int s0 = g_srcs[off + j];
        int s1 = g_srcs[off + j + 1];
        int s2 = g_srcs[off + j + 2];
        int s3 = g_srcs[off + j + 3];
        float4 v0 = __ldg(&in[(size_t)s0 * 16 + c4]);
        float4 v1 = __ldg(&in[(size_t)s1 * 16 + c4]);
        float4 v2 = __ldg(&in[(size_t)s2 * 16 + c4]);
        float4 v3 = __ldg(&in[(size_t)s3 * 16 + c4]);
        xf_acc(acc, v0, a4, b4, MODE);
        xf_acc(acc, v1, a4, b4, MODE);
        xf_acc(acc, v2, a4, b4, MODE);
        xf_acc(acc, v3, a4, b4, MODE);
    }
    for (; j < d; j++) {
        int s0 = g_srcs[off + j];
        float4 v0 = __ldg(&in[(size_t)s0 * 16 + c4]);
        xf_acc(acc, v0, a4, b4, MODE);
    }

    float inv = 1.f / (float)max(d, 1);
    acc.x *= inv; acc.y *= inv; acc.z *= inv; acc.w *= inv;
    ((float4*)g_agg)[(size_t)node * 16 + c4] = acc;
}

// ---------------- fused dual GEMM + BN-stats epilogue ----------------
// out = g_agg@Wl^T + bl + X@Wr^T ; block-reduced sum/sumsq atomically into g_sums.
// MODE 0: X = Xext raw, out = g_pre.  MODE 1: X = g_pre w/ BN1+ReLU, out = g_act1.
template <int MODE>
__global__ void k_gemm(const float* __restrict__ Xext,
                       const float* __restrict__ Wl, const float* __restrict__ bl,
                       const float* __restrict__ Wr) {
    __shared__ float xs[64 * 64];   // [k][n] swizzled ; reused for stats reduction
    __shared__ float ws[64 * 64];   // [k][c] swizzled
    int tid = threadIdx.x;
    int node0 = blockIdx.x * 64;
    const float* __restrict__ Xp  = MODE ? (const float*)g_pre : Xext;
    float* __restrict__       out = MODE ? (float*)g_act1 : (float*)g_pre;

    int c0 = (tid & 15) * 4;
    int n0 = (tid >> 4) * 4;

    float acc[4][4];
#pragma unroll
    for (int j = 0; j < 4; j++) {
        float b = __ldg(&bl[c0 + j]);
#pragma unroll
        for (int i = 0; i < 4; i++) acc[i][j] = b;
    }

#pragma unroll
    for (int ph = 0; ph < 2; ph++) {
        const float* __restrict__ src = ph ? Xp : (const float*)g_agg;
        const float* __restrict__ W   = ph ? Wr : Wl;
        const bool bn = MODE && (ph == 1);

        for (int idx = tid; idx < 4096; idx += 256) {
            int n = idx >> 6, k = idx & 63;
            int gn = node0 + n;
            float v = (gn < NN) ? src[(size_t)gn * HD + k] : 0.f;
            if (bn) v = fmaxf(fmaf(v, __ldg(&g_bnA[k]), __ldg(&g_bnB[k])), 0.f);
            xs[k * 64 + (n ^ ((k & 15) << 2))] = v;
        }
        for (int idx = tid; idx < 4096; idx += 256) {
            int c = idx >> 6, k = idx & 63;
            ws[k * 64 + (c ^ ((k & 15) << 2))] = W[idx];
        }
        __syncthreads();

#pragma unroll 8
        for (int k = 0; k < 64; k++) {
            int sw = (k & 15) << 2;
            float4 wv = *reinterpret_cast<const float4*>(&ws[k * 64 + (c0 ^ sw)]);
            float4 xv = *reinterpret_cast<const float4*>(&xs[k * 64 + (n0 ^ sw)]);
            float wr[4] = {wv.x, wv.y, wv.z, wv.w};
            float xr[4] = {xv.x, xv.y, xv.z, xv.w};
#pragma unroll
            for (int i = 0; i < 4; i++)
#pragma unroll
                for (int j = 0; j < 4; j++)
                    acc[i][j] += xr[i] * wr[j];
        }
        __syncthreads();
    }

    // store output
#pragma unroll
    for (int i = 0; i < 4; i++) {
        int gn = node0 + n0 + i;
        if (gn < NN) {
            float4 v = make_float4(acc[i][0], acc[i][1], acc[i][2], acc[i][3]);
            *reinterpret_cast<float4*>(&out[(size_t)gn * HD + c0]) = v;
        }
    }

    // BN stats epilogue: per-thread channel partials over valid nodes
    float s[4] = {0.f, 0.f, 0.f, 0.f};
    float q[4] = {0.f, 0.f, 0.f, 0.f};
#pragma unroll
    for (int i = 0; i < 4; i++) {
        if (node0 + n0 + i < NN) {
#pragma unroll
            for (int j = 0; j < 4; j++) {
                float v = acc[i][j];
                s[j] += v; q[j] += v * v;
            }
        }
    }
    float* rs = xs;            // 16 x 64
    float* rq = xs + 1024;     // 16 x 64
    int grp = tid >> 4;
#pragma unroll
    for (int j = 0; j < 4; j++) {
        rs[grp * 64 + c0 + j] = s[j];
        rq[grp * 64 + c0 + j] = q[j];
    }
    __syncthreads();
    if (tid < 64) {
        float ts = 0.f, tq = 0.f;
#pragma unroll
        for (int g = 0; g < 16; g++) {
            ts += rs[g * 64 + tid];
            tq += rq[g * 64 + tid];
        }
        atomicAdd(&g_sums[tid], ts);
        atomicAdd(&g_sums[HD + tid], tq);
    }
}

// ---------------- BN finalize ----------------
__global__ void k_zero_sums() {
    int i = threadIdx.x;
    if (i < 2 * HD) g_sums[i] = 0.f;
}

__global__ void k_bnfin(const float* __restrict__ g, const float* __restrict__ beta) {
    int ch = threadIdx.x;
    if (ch < HD) {
        float mu  = g_sums[ch] / (float)NN;
        float var = g_sums[HD + ch] / (float)NN - mu * mu;
        float a   = g[ch] * rsqrtf(var + BN_EPS);
        g_bnA[ch] = a;
        g_bnB[ch] = beta[ch] - mu * a;
    }
}

// ---------------- decoder: h = relu(bn2(g_act1)) -> hout ; logits = h@Wd^T + bd ----------------
__global__ void k_dec(const float* __restrict__ Wd, const float* __restrict__ bd,
                      float* __restrict__ hout, float* __restrict__ logits) {
    __shared__ float wd[CC * 65];
    __shared__ float hs[128 * 65];
    int tid = threadIdx.x;
    for (int idx = tid; idx < CC * HD; idx += 256) {
        int c = idx / HD, k = idx % HD;
        wd[c * 65 + k] = Wd[idx];
    }
    int node0 = blockIdx.x * 128;
    for (int idx = tid; idx < 128 * HD; idx += 256) {
        int n = idx >> 6, k = idx & 63;
        int gn = node0 + n;
        float y = 0.f;
        if (gn < NN) {
            float v = g_act1[(size_t)gn * HD + k];
            y = fmaxf(fmaf(v, __ldg(&g_bnA[k]), __ldg(&g_bnB[k])), 0.f);
            hout[(size_t)gn * HD + k] = y;
        }
        hs[n * 65 + k] = y;
    }
    __syncthreads();

    int c0 = (tid & 3) * 10;
    int n0 = (tid >> 2) * 2;

    float acc[2][10];
#pragma unroll
    for (int j = 0; j < 10; j++) {
        float b = __ldg(&bd[c0 + j]);
        acc[0][j] = b; acc[1][j] = b;
    }
#pragma unroll 4
    for (int k = 0; k < 64; k++) {
        float w[10];
#pragma unroll
        for (int j = 0; j < 10; j++) w[j] = wd[(c0 + j) * 65 + k];
        float a0 = hs[n0 * 65 + k];
        float a1 = hs[(n0 + 1) * 65 + k];
#pragma unroll
        for (int j = 0; j < 10; j++) {
            acc[0][j] += a0 * w[j];
            acc[1][j] += a1 * w[j];
        }
    }
#pragma unroll
    for (int i = 0; i < 2; i++) {
        int gn = node0 + n0 + i;
        if (gn < NN) {
#pragma unroll
            for (int j = 0; j < 10; j++)
                logits[(size_t)gn * CC + c0 + j] = acc[i][j];
        }
    }
}

// ---------------- launcher: ONLY kernel launches ----------------
extern "C" void kernel_launch(void* const* d_in, const int* in_sizes, int n_in,
                              void* d_out, int out_size) {
    const float* x   = (const float*)d_in[0];
    const int*   ei  = (const int*)d_in[1];
    const float* W1l = (const float*)d_in[2];
    const float* b1l = (const float*)d_in[3];
    const float* W1r = (const float*)d_in[4];
    const float* g1  = (const float*)d_in[5];
    const float* be1 = (const float*)d_in[6];
    const float* W2l = (const float*)d_in[7];
    const float* b2l = (const float*)d_in[8];
    const float* W2r = (const float*)d_in[9];
    const float* g2  = (const float*)d_in[10];
    const float* be2 = (const float*)d_in[11];
    const float* Wd  = (const float*)d_in[12];
    const float* bd  = (const float*)d_in[13];

    float* outp   = (float*)d_out;
    float* logits = outp;                       // [N, C]
    float* hout   = outp + (size_t)NN * CC;     // [N, H]

    // CSR build
    k_detect<<<1, 32>>>(ei);
    k_zero_counters<<<(NN + 255) / 256, 256>>>();
    k_hist<<<(EE + 255) / 256, 256>>>(ei);
    k_scan1<<<SCAN_NBLK, 1024>>>();
    k_scan2<<<1, 128>>>();
    k_scan3<<<(NN + 255) / 256, 256>>>();
    k_build<<<(EE + 255) / 256, 256>>>(ei);

    // Layer 1: agg(x) -> gemm(+stats) -> bnfin
    k_agg<0><<<(NN + 7) / 8, 128>>>(x);
    k_zero_sums<<<1, 128>>>();
    k_gemm<0><<<(NN + 63) / 64, 256>>>(x, W1l, b1l, W1r);
    k_bnfin<<<1, 64>>>(g1, be1);

    // Layer 2: agg(bn1(pre)) -> gemm(bn1 on root, +stats) -> bnfin
    k_agg<1><<<(NN + 7) / 8, 128>>>(nullptr);
    k_zero_sums<<<1, 128>>>();
    k_gemm<1><<<(NN + 63) / 64, 256>>>(nullptr, W2l, b2l, W2r);
    k_bnfin<<<1, 64>>>(g2, be2);

    // Decoder (applies bn2+relu, emits hout and logits)
    k_dec<<<(NN + 127) / 128, 256>>>(Wd, bd, hout, logits);
}

// round 9
// speedup vs baseline: 1.5097x; 1.0267x over previous
#include <cuda_runtime.h>

#define NN 100000
#define EE 1600000
#define HD 64
#define CC 40
#define BN_EPS 1e-5f
#define SCAN_NBLK ((NN + 1023) / 1024)   // 98

// ---------------- device scratch (static globals; no runtime allocation) ----------------
__device__ int   g_mode;          // 0 = edge_index int32, 1 = int64
__device__ int   g_edst[EE];
__device__ int   g_deg[NN];
__device__ int   g_off[NN];       // scan3: start offsets; after build: end offsets
__device__ int   g_srcs[EE];
__device__ int   g_bsum[SCAN_NBLK];
__device__ int   g_bpre[SCAN_NBLK];
__device__ __align__(16) float g_agg [NN * HD];
__device__ __align__(16) float g_pre [NN * HD];   // layer-1 pre-activation
__device__ __align__(16) float g_act1[NN * HD];   // layer-2 pre-activation
__device__ float g_sums1[2 * HD];                 // layer-1 BN raw stats
__device__ float g_sums2[2 * HD];                 // layer-2 BN raw stats

// ---------------- init: zero degrees + edge dtype detection ----------------
__global__ void k_init(const int* __restrict__ p32) {
    int i = blockIdx.x * blockDim.x + threadIdx.x;
    if (i < NN) g_deg[i] = 0;
    if (i == 0) {
        int allz = 1;
        for (int t = 0; t < 32; t++)
            if (p32[2 * t + 1] != 0) allz = 0;
        g_mode = allz;   // int64 data: high words of first 32 ids are all zero
    }
}

__global__ void k_hist(const int* __restrict__ p32) {
    int e = blockIdx.x * blockDim.x + threadIdx.x;
    if (e < EE) {
        int d = g_mode ? p32[2 * EE + 2 * e] : p32[EE + e];
        g_edst[e] = d;
        atomicAdd(&g_deg[d], 1);
    }
}

__global__ void k_scan1() {
    __shared__ int ss[1024];
    int tid = threadIdx.x;
    int i = blockIdx.x * 1024 + tid;
    int v = (i < NN) ? g_deg[i] : 0;
    ss[tid] = v;
    __syncthreads();
#pragma unroll
    for (int d = 1; d < 1024; d <<= 1) {
        int t = (tid >= d) ? ss[tid - d] : 0;
        __syncthreads();
        ss[tid] += t;
        __syncthreads();
    }
    if (i < NN) g_off[i] = ss[tid] - v;
    if (tid == 1023) g_bsum[blockIdx.x] = ss[1023];
}

__global__ void k_scan2() {
    __shared__ int ss[128];
    int tid = threadIdx.x;
    int v = (tid < SCAN_NBLK) ? g_bsum[tid] : 0;
    ss[tid] = v;
    __syncthreads();
#pragma unroll
    for (int d = 1; d < 128; d <<= 1) {
        int t = (tid >= d) ? ss[tid - d] : 0;
        __syncthreads();
        ss[tid] += t;
        __syncthreads();
    }
    if (tid < SCAN_NBLK) g_bpre[tid] = ss[tid] - v;
}

__global__ void k_scan3() {
    int i = blockIdx.x * blockDim.x + threadIdx.x;
    if (i < NN) g_off[i] += g_bpre[i >> 10];
}

// scatter: atomic cursor directly on g_off (returned old value = slot)
__global__ void k_build(const int* __restrict__ p32) {
    int e = blockIdx.x * blockDim.x + threadIdx.x;
    if (e < EE) {
        int s = g_mode ? p32[2 * e] : p32[e];
        int d = g_edst[e];
        int p = atomicAdd(&g_off[d], 1);
        g_srcs[p] = s;
    }
}

// ---------------- mean aggregation: 16 threads/node, float4 gather ----------------
// MODE 0: in = xin raw; block 0 zeroes g_sums1.
// MODE 1: in = g_pre with BN1+ReLU (recomputed per block from g_sums1); block 0 zeroes g_sums2.
__device__ __forceinline__ void xf_acc(float4& acc, float4 v,
                                       const float4& a4, const float4& b4, int mode) {
    if (mode) {
        v.x = fmaxf(fmaf(v.x, a4.x, b4.x), 0.f);
        v.y = fmaxf(fmaf(v.y, a4.y, b4.y), 0.f);
        v.z = fmaxf(fmaf(v.z, a4.z, b4.z), 0.f);
        v.w = fmaxf(fmaf(v.w, a4.w, b4.w), 0.f);
    }
    acc.x += v.x; acc.y += v.y; acc.z += v.z; acc.w += v.w;
}

template <int MODE>
__global__ void k_agg(const float* __restrict__ xin,
                      const float* __restrict__ gamma, const float* __restrict__ beta) {
    __shared__ __align__(16) float sa[HD], sb[HD];
    const float4* __restrict__ in = MODE ? (const float4*)g_pre : (const float4*)xin;
    int tid = threadIdx.x;

    if (blockIdx.x == 0) {           // zero the NEXT layer's stats buffer
        if (MODE) g_sums2[tid] = 0.f; else g_sums1[tid] = 0.f;
    }
    if (MODE) {
        if (tid < HD) {
            float mu  = g_sums1[tid] * (1.f / (float)NN);
            float var = g_sums1[HD + tid] * (1.f / (float)NN) - mu * mu;
            float a   = gamma[tid] * rsqrtf(var + BN_EPS);
            sa[tid] = a;
            sb[tid] = beta[tid] - mu * a;
        }
        __syncthreads();
    }

    int node = blockIdx.x * 8 + (tid >> 4);
    int c4   = tid & 15;
    if (node >= NN) return;

    float4 a4 = make_float4(1.f, 1.f, 1.f, 1.f);
    float4 b4 = make_float4(0.f, 0.f, 0.f, 0.f);
    if (MODE) {
        a4 = ((const float4*)sa)[c4];
        b4 = ((const float4*)sb)[c4];
    }

    int d   = g_deg[node];
    int off = g_off[node] - d;       // g_off holds END offsets after k_build
    float4 acc = make_float4(0.f, 0.f, 0.f, 0.f);

    int j = 0;
    for (; j + 4 <= d; j += 4) {
        int s0 = g_srcs[off + j];
        int s1 = g_srcs[off + j + 1];
        int s2 = g_srcs[off + j + 2];
        int s3 = g_srcs[off + j + 3];
        float4 v0 = __ldg(&in[(size_t)s0 * 16 + c4]);
        float4 v1 = __ldg(&in[(size_t)s1 * 16 + c4]);
        float4 v2 = __ldg(&in[(size_t)s2 * 16 + c4]);
        float4 v3 = __ldg(&in[(size_t)s3 * 16 + c4]);
        xf_acc(acc, v0, a4, b4, MODE);
        xf_acc(acc, v1, a4, b4, MODE);
        xf_acc(acc, v2, a4, b4, MODE);
        xf_acc(acc, v3, a4, b4, MODE);
    }
    for (; j < d; j++) {
        int s0 = g_srcs[off + j];
        float4 v0 = __ldg(&in[(size_t)s0 * 16 + c4]);
        xf_acc(acc, v0, a4, b4, MODE);
    }

    float inv = 1.f / (float)max(d, 1);
    acc.x *= inv; acc.y *= inv; acc.z *= inv; acc.w *= inv;
    ((float4*)g_agg)[(size_t)node * 16 + c4] = acc;
}

// ---------------- fused dual GEMM + BN-stats epilogue ----------------
// out = g_agg@Wl^T + bl + X@Wr^T ; block-reduced sum/sumsq atomically into g_sumsX.
// MODE 0: X = Xext raw, out = g_pre, stats -> g_sums1.
// MODE 1: X = g_pre with BN1+ReLU (recomputed from g_sums1), out = g_act1, stats -> g_sums2.
template <int MODE>
__global__ void k_gemm(const float* __restrict__ Xext,
                       const float* __restrict__ Wl, const float* __restrict__ bl,
                       const float* __restrict__ Wr,
                       const float* __restrict__ gamma, const float* __restrict__ beta) {
    __shared__ float xs[64 * 64];   // [k][n] swizzled ; reused for stats reduction
    __shared__ float ws[64 * 64];   // [k][c] swizzled
    __shared__ float sa[HD], sb[HD];
    int tid = threadIdx.x;
    int node0 = blockIdx.x * 64;
    const float* __restrict__ Xp  = MODE ? (const float*)g_pre : Xext;
    float* __restrict__       out = MODE ? (float*)g_act1 : (float*)g_pre;

    int c0 = (tid & 15) * 4;
    int n0 = (tid >> 4) * 4;

    float acc[4][4];
#pragma unroll
    for (int j = 0; j < 4; j++) {
        float b = __ldg(&bl[c0 + j]);
#pragma unroll
        for (int i = 0; i < 4; i++) acc[i][j] = b;
    }

#pragma unroll
    for (int ph = 0; ph < 2; ph++) {
        const float* __restrict__ src = ph ? Xp : (const float*)g_agg;
        const float* __restrict__ W   = ph ? Wr : Wl;
        const bool bn = MODE && (ph == 1);

        if (MODE && ph == 0 && tid < HD) {   // compute BN1 coeffs once, covered by sync below
            float mu  = g_sums1[tid] * (1.f / (float)NN);
            float var = g_sums1[HD + tid] * (1.f / (float)NN) - mu * mu;
            float a   = gamma[tid] * rsqrtf(var + BN_EPS);
            sa[tid] = a;
            sb[tid] = beta[tid] - mu * a;
        }

        for (int idx = tid; idx < 4096; idx += 256) {
            int n = idx >> 6, k = idx & 63;
            int gn = node0 + n;
            float v = (gn < NN) ? src[(size_t)gn * HD + k] : 0.f;
            if (bn) v = fmaxf(fmaf(v, sa[k], sb[k]), 0.f);
            xs[k * 64 + (n ^ ((k & 15) << 2))] = v;
        }
        for (int idx = tid; idx < 4096; idx += 256) {
            int c = idx >> 6, k = idx & 63;
            ws[k * 64 + (c ^ ((k & 15) << 2))] = W[idx];
        }
        __syncthreads();

#pragma unroll 8
        for (int k = 0; k < 64; k++) {
            int sw = (k & 15) << 2;
            float4 wv = *reinterpret_cast<const float4*>(&ws[k * 64 + (c0 ^ sw)]);
            float4 xv = *reinterpret_cast<const float4*>(&xs[k * 64 + (n0 ^ sw)]);
            float wr[4] = {wv.x, wv.y, wv.z, wv.w};
            float xr[4] = {xv.x, xv.y, xv.z, xv.w};
#pragma unroll
            for (int i = 0; i < 4; i++)
#pragma unroll
                for (int j = 0; j < 4; j++)
                    acc[i][j] += xr[i] * wr[j];
        }
        __syncthreads();
    }

    // store output
#pragma unroll
    for (int i = 0; i < 4; i++) {
        int gn = node0 + n0 + i;
        if (gn < NN) {
            float4 v = make_float4(acc[i][0], acc[i][1], acc[i][2], acc[i][3]);
            *reinterpret_cast<float4*>(&out[(size_t)gn * HD + c0]) = v;
        }
    }

    // BN stats epilogue
    float s[4] = {0.f, 0.f, 0.f, 0.f};
    float q[4] = {0.f, 0.f, 0.f, 0.f};
#pragma unroll
    for (int i = 0; i < 4; i++) {
        if (node0 + n0 + i < NN) {
#pragma unroll
            for (int j = 0; j < 4; j++) {
                float v = acc[i][j];
                s[j] += v; q[j] += v * v;
            }
        }
    }
    float* rs = xs;            // 16 x 64
    float* rq = xs + 1024;     // 16 x 64
    int grp = tid >> 4;
#pragma unroll
    for (int j = 0; j < 4; j++) {
        rs[grp * 64 + c0 + j] = s[j];
        rq[grp * 64 + c0 + j] = q[j];
    }
    __syncthreads();
    if (tid < 64) {
        float ts = 0.f, tq = 0.f;
#pragma unroll
        for (int g = 0; g < 16; g++) {
            ts += rs[g * 64 + tid];
            tq += rq[g * 64 + tid];
        }
        float* dst = MODE ? g_sums2 : g_sums1;
        atomicAdd(&dst[tid], ts);
        atomicAdd(&dst[HD + tid], tq);
    }
}

// ---------------- decoder: h = relu(bn2(g_act1)) -> hout ; logits = h@Wd^T + bd ----------------
__global__ void k_dec(const float* __restrict__ Wd, const float* __restrict__ bd,
                      const float* __restrict__ gamma, const float* __restrict__ beta,
                      float* __restrict__ hout, float* __restrict__ logits) {
    __shared__ float wd[CC * 65];
    __shared__ float hs[128 * 65];
    __shared__ float sa[HD], sb[HD];
    int tid = threadIdx.x;

    if (tid < HD) {
        float mu  = g_sums2[tid] * (1.f / (float)NN);
        float var = g_sums2[HD + tid] * (1.f / (float)NN) - mu * mu;
        float a   = gamma[tid] * rsqrtf(var + BN_EPS);
        sa[tid] = a;
        sb[tid] = beta[tid] - mu * a;
    }
    for (int idx = tid; idx < CC * HD; idx += 256) {
        int c = idx / HD, k = idx % HD;
        wd[c * 65 + k] = Wd[idx];
    }
    __syncthreads();

    int node0 = blockIdx.x * 128;
    for (int idx = tid; idx < 128 * HD; idx += 256) {
        int n = idx >> 6, k = idx & 63;
        int gn = node0 + n;
        float y = 0.f;
        if (gn < NN) {
            float v = g_act1[(size_t)gn * HD + k];
            y = fmaxf(fmaf(v, sa[k], sb[k]), 0.f);
            hout[(size_t)gn * HD + k] = y;
        }
        hs[n * 65 + k] = y;
    }
    __syncthreads();

    int c0 = (tid & 3) * 10;
    int n0 = (tid >> 2) * 2;

    float acc[2][10];
#pragma unroll
    for (int j = 0; j < 10; j++) {
        float b = __ldg(&bd[c0 + j]);
        acc[0][j] = b; acc[1][j] = b;
    }
#pragma unroll 4
    for (int k = 0; k < 64; k++) {
        float w[10];
#pragma unroll
        for (int j = 0; j < 10; j++) w[j] = wd[(c0 + j) * 65 + k];
        float a0 = hs[n0 * 65 + k];
        float a1 = hs[(n0 + 1) * 65 + k];
#pragma unroll
        for (int j = 0; j < 10; j++) {
            acc[0][j] += a0 * w[j];
            acc[1][j] += a1 * w[j];
        }
    }
#pragma unroll
    for (int i = 0; i < 2; i++) {
        int gn = node0 + n0 + i;
        if (gn < NN) {
#pragma unroll
            for (int j = 0; j < 10; j++)
                logits[(size_t)gn * CC + c0 + j] = acc[i][j];
        }
    }
}

// ---------------- launcher: ONLY kernel launches (11 total) ----------------
extern "C" void kernel_launch(void* const* d_in, const int* in_sizes, int n_in,
                              void* d_out, int out_size) {
    const float* x   = (const float*)d_in[0];
    const int*   ei  = (const int*)d_in[1];
    const float* W1l = (const float*)d_in[2];
    const float* b1l = (const float*)d_in[3];
    const float* W1r = (const float*)d_in[4];
    const float* g1  = (const float*)d_in[5];
    const float* be1 = (const float*)d_in[6];
    const float* W2l = (const float*)d_in[7];
    const float* b2l = (const float*)d_in[8];
    const float* W2r = (const float*)d_in[9];
    const float* g2  = (const float*)d_in[10];
    const float* be2 = (const float*)d_in[11];
    const float* Wd  = (const float*)d_in[12];
    const float* bd  = (const float*)d_in[13];

    float* outp   = (float*)d_out;
    float* logits = outp;                       // [N, C]
    float* hout   = outp + (size_t)NN * CC;     // [N, H]

    // CSR build
    k_init<<<(NN + 255) / 256, 256>>>(ei);
    k_hist<<<(EE + 255) / 256, 256>>>(ei);
    k_scan1<<<SCAN_NBLK, 1024>>>();
    k_scan2<<<1, 128>>>();
    k_scan3<<<(NN + 255) / 256, 256>>>();
    k_build<<<(EE + 255) / 256, 256>>>(ei);

    // Layer 1
    k_agg<0><<<(NN + 7) / 8, 128>>>(x, nullptr, nullptr);
    k_gemm<0><<<(NN + 63) / 64, 256>>>(x, W1l, b1l, W1r, nullptr, nullptr);

    // Layer 2
    k_agg<1><<<(NN + 7) / 8, 128>>>(nullptr, g1, be1);
    k_gemm<1><<<(NN + 63) / 64, 256>>>(nullptr, W2l, b2l, W2r, g1, be1);

    // Decoder
    k_dec<<<(NN + 127) / 128, 256>>>(Wd, bd, g2, be2, hout, logits);
}